// round 17
// baseline (speedup 1.0000x reference)
#include <cuda_runtime.h>
#include <cuda_bf16.h>
#include <cuda_fp16.h>
#include <math.h>
#include <stdint.h>

#define CDIM   192
#define KVDIM  384
#define HEADS  6
#define CPH    32
#define WIDTH  160
#define HW     25600          // 160*160
#define BATCH  8
#define NSPLIT 16
#define W4     40             // WIDTH/4 float4 per image row

// ---------------- scratch (device globals; no allocation) ----------------
__device__ float g_q   [(size_t)BATCH * CDIM  * HW];   // q after 1x1
__device__ float g_kv  [(size_t)BATCH * KVDIM * HW];   // kv after 1x1
__device__ float g_qd  [(size_t)BATCH * CDIM  * HW];   // q after dw3x3
__device__ float g_kvd [(size_t)BATCH * KVDIM * HW];   // k after dw3x3 (first half used)
__device__ float g_S   [BATCH * HEADS * CPH * CPH];    // raw gram
__device__ float g_NQ  [BATCH * HEADS * CPH];          // sum q^2
__device__ float g_NK  [BATCH * HEADS * CPH];          // sum k^2
__device__ float g_A   [BATCH * HEADS * CPH * CPH];    // softmax(attn)
// fp16 operands for tensor-core GEMMs
__device__ __half g_Wq16 [CDIM  * CDIM];
__device__ __half g_Wkv16[KVDIM * CDIM];
__device__ __half g_M16  [BATCH * CDIM * CDIM];        // W_out @ blockdiag(A)
__device__ __half g_Xq16 [(size_t)BATCH * CDIM * HW];  // x_query
__device__ __half g_Xkv16[(size_t)BATCH * CDIM * HW];  // x_key_value (192 ch)
__device__ __half g_V16  [(size_t)BATCH * CDIM * HW];  // v after dw3x3

// ================= warp-MMA + cp.async helpers (arch-agnostic PTX) ========
__device__ __forceinline__ uint32_t smem_u32(const void* p) {
    uint32_t a;
    asm("{ .reg .u64 t; cvta.to.shared.u64 t, %1; cvt.u32.u64 %0, t; }" : "=r"(a) : "l"(p));
    return a;
}
__device__ __forceinline__ void ldsm_x4(uint32_t (&r)[4], uint32_t addr) {
    asm volatile("ldmatrix.sync.aligned.m8n8.x4.shared.b16 {%0,%1,%2,%3}, [%4];"
        : "=r"(r[0]), "=r"(r[1]), "=r"(r[2]), "=r"(r[3]) : "r"(addr));
}
__device__ __forceinline__ void ldsm_x4_t(uint32_t (&r)[4], uint32_t addr) {
    asm volatile("ldmatrix.sync.aligned.m8n8.x4.trans.shared.b16 {%0,%1,%2,%3}, [%4];"
        : "=r"(r[0]), "=r"(r[1]), "=r"(r[2]), "=r"(r[3]) : "r"(addr));
}
__device__ __forceinline__ void mma_fp16(float (&d)[4], const uint32_t (&a)[4],
                                         uint32_t b0, uint32_t b1) {
    asm volatile("mma.sync.aligned.m16n8k16.row.col.f32.f16.f16.f32 "
        "{%0,%1,%2,%3}, {%4,%5,%6,%7}, {%8,%9}, {%0,%1,%2,%3};"
        : "+f"(d[0]), "+f"(d[1]), "+f"(d[2]), "+f"(d[3])
        : "r"(a[0]), "r"(a[1]), "r"(a[2]), "r"(a[3]), "r"(b0), "r"(b1));
}
#define CP16(dst, src) \
    asm volatile("cp.async.cg.shared.global [%0], [%1], 16;" :: "r"(dst), "l"(src))
#define CP_COMMIT() asm volatile("cp.async.commit_group;" ::: "memory")
#define CP_WAIT1()  asm volatile("cp.async.wait_group 1;" ::: "memory")
#define CP_WAIT0()  asm volatile("cp.async.wait_group 0;" ::: "memory")

// ============ fp16 tensor-core GEMM, BK=64, 2-stage double buffer =========
// (unchanged from R16 — 724 µs baseline)
#define APAD 72     // A row = 144 B
#define BPAD 136    // B row = 272 B
#define A_SZ (64*APAD*2)      // 9216
#define B_SZ (64*BPAD*2)      // 17408
#define STG_SZ (A_SZ + B_SZ)  // 26624
#define SM_TOTAL (2*STG_SZ)   // 53248
__device__ __forceinline__ uint32_t aOff(int s) { return (uint32_t)s * STG_SZ; }
__device__ __forceinline__ uint32_t bOff(int s) { return (uint32_t)s * STG_SZ + A_SZ; }

__global__ __launch_bounds__(256, 3) void gemm_fp16(
    const __half* __restrict__ Ax, const __half* __restrict__ Bx,
    float* __restrict__ Y, int O, long wBatch, long xBatch)
{
    extern __shared__ char smem[];
    const uint32_t sb = smem_u32(smem);

    const int tid  = threadIdx.x;
    const int wid  = tid >> 5, lane = tid & 31;
    const int wm   = wid >> 2;          // 0..1
    const int wn   = wid & 3;           // 0..3
    const int n0   = blockIdx.x * 128;
    const int o0   = blockIdx.y * 64;
    const int b    = blockIdx.z;

    const __half* Ab = Ax + (size_t)b * wBatch + (size_t)o0 * CDIM;
    const __half* Bb = Bx + (size_t)b * xBatch + n0;

    const int a0m = tid >> 3,          a0k = (tid & 7) * 8;
    const int a1m = (tid + 256) >> 3,  a1k = (tid & 7) * 8;
    const int bkc[4] = { tid >> 4, (tid + 256) >> 4, (tid + 512) >> 4, (tid + 768) >> 4 };
    const int bnc    = (tid & 15) * 8;

    const int aRow = (lane & 7) + ((lane >> 3) & 1) * 8;
    const int aCol = ((lane >> 4) & 1) * 8;
    const int bRow = aRow, bCol = aCol;

    float acc[2][4][4] = {};

    {
        CP16(sb + aOff(0) + (a0m*APAD + a0k)*2, Ab + (size_t)a0m * CDIM + a0k);
        CP16(sb + aOff(0) + (a1m*APAD + a1k)*2, Ab + (size_t)a1m * CDIM + a1k);
        #pragma unroll
        for (int i = 0; i < 4; i++)
            CP16(sb + bOff(0) + (bkc[i]*BPAD + bnc)*2, Bb + (size_t)bkc[i] * HW + bnc);
        CP_COMMIT();
    }

    int buf = 0;
    #pragma unroll 1
    for (int kb = 0; kb < 3; kb++) {
        if (kb < 2) {
            const int k0 = (kb + 1) * 64;
            const int nb = buf ^ 1;
            CP16(sb + aOff(nb) + (a0m*APAD + a0k)*2, Ab + (size_t)a0m * CDIM + k0 + a0k);
            CP16(sb + aOff(nb) + (a1m*APAD + a1k)*2, Ab + (size_t)a1m * CDIM + k0 + a1k);
            #pragma unroll
            for (int i = 0; i < 4; i++)
                CP16(sb + bOff(nb) + (bkc[i]*BPAD + bnc)*2, Bb + (size_t)(k0 + bkc[i]) * HW + bnc);
            CP_COMMIT();
            CP_WAIT1();
        } else {
            CP_WAIT0();
        }
        __syncthreads();

        #pragma unroll
        for (int ks = 0; ks < 4; ks++) {
            uint32_t ah[2][4], bh[2][4];
            #pragma unroll
            for (int mt = 0; mt < 2; mt++) {
                uint32_t off = (uint32_t)((wm * 32 + mt * 16 + aRow) * APAD + ks * 16 + aCol) * 2;
                ldsm_x4(ah[mt], sb + aOff(buf) + off);
            }
            #pragma unroll
            for (int np = 0; np < 2; np++) {
                uint32_t off = (uint32_t)((ks * 16 + bRow) * BPAD + wn * 32 + np * 16 + bCol) * 2;
                ldsm_x4_t(bh[np], sb + bOff(buf) + off);
            }
            #pragma unroll
            for (int mt = 0; mt < 2; mt++)
                #pragma unroll
                for (int np = 0; np < 2; np++)
                    #pragma unroll
                    for (int s = 0; s < 2; s++)
                        mma_fp16(acc[mt][np*2+s], ah[mt], bh[np][s*2], bh[np][s*2+1]);
        }
        __syncthreads();
        buf ^= 1;
    }

    const int g = lane >> 2, cc = (lane & 3) * 2;
    #pragma unroll
    for (int mt = 0; mt < 2; mt++) {
        #pragma unroll
        for (int nt = 0; nt < 4; nt++) {
            int orow = o0 + wm * 32 + mt * 16 + g;
            int ncol = n0 + wn * 32 + nt * 8 + cc;
            float2 v0 = make_float2(acc[mt][nt][0], acc[mt][nt][1]);
            float2 v1 = make_float2(acc[mt][nt][2], acc[mt][nt][3]);
            *(float2*)&Y[((size_t)b * O + orow    ) * HW + ncol] = v0;
            *(float2*)&Y[((size_t)b * O + orow + 8) * HW + ncol] = v1;
        }
    }
}

// ---------------- convert fp32 weights to fp16 ----------------------------
__global__ void convert_w(const float* __restrict__ wq, const float* __restrict__ wkv) {
    int i = blockIdx.x * 256 + threadIdx.x;
    if (i < CDIM * CDIM)  g_Wq16[i]  = __float2half_rn(wq[i]);
    if (i < KVDIM * CDIM) g_Wkv16[i] = __float2half_rn(wkv[i]);
}

// ---------------- convert fp32 activations to fp16 ------------------------
__global__ __launch_bounds__(256) void convert_x(
    const float* __restrict__ xq, const float* __restrict__ xkv)
{
    const size_t i = (size_t)blockIdx.x * 256 + threadIdx.x;      // float4 index
    float4 v = ((const float4*)xq)[i];
    __half2 a = __floats2half2_rn(v.x, v.y);
    __half2 b = __floats2half2_rn(v.z, v.w);
    ((uint2*)g_Xq16)[i] = make_uint2(*(uint32_t*)&a, *(uint32_t*)&b);
    v = ((const float4*)xkv)[i];
    a = __floats2half2_rn(v.x, v.y);
    b = __floats2half2_rn(v.z, v.w);
    ((uint2*)g_Xkv16)[i] = make_uint2(*(uint32_t*)&a, *(uint32_t*)&b);
}

// =============== depthwise 3x3 v3 — float4 vectorized =====================
// Block (40, 8): thread (tx, ty) computes output row r0+ty, cols 4tx..4tx+3.
// smem tile: 10 rows x 40 float4. 3 LDS.128 per input row per thread.
__device__ __forceinline__ float4 dw_compute_row4(
    const float4 s[10][W4], int tx, int ty, const float* wp)
{
    float4 o = make_float4(0.f, 0.f, 0.f, 0.f);
    #pragma unroll
    for (int rr = 0; rr < 3; rr++) {
        float w0 = wp[rr * 3 + 0], w1 = wp[rr * 3 + 1], w2 = wp[rr * 3 + 2];
        float4 C = s[ty + rr][tx];
        float  l = (tx > 0)      ? s[ty + rr][tx - 1].w : 0.f;
        float  r = (tx < W4 - 1) ? s[ty + rr][tx + 1].x : 0.f;
        o.x += w0 * l   + w1 * C.x + w2 * C.y;
        o.y += w0 * C.x + w1 * C.y + w2 * C.z;
        o.z += w0 * C.y + w1 * C.z + w2 * C.w;
        o.w += w0 * C.z + w1 * C.w + w2 * r;
    }
    return o;
}
__device__ __forceinline__ void dw_stage(
    float4 s[10][W4], const float* xp, int r0, int t)
{
    #pragma unroll
    for (int i = 0; i < 2; i++) {
        int idx = t + i * 320;
        if (idx < 400) {
            int rr = idx / W4, cc = idx % W4;
            int r = r0 - 1 + rr;
            s[rr][cc] = (r >= 0 && r < WIDTH)
                ? ((const float4*)xp)[r * W4 + cc]
                : make_float4(0.f, 0.f, 0.f, 0.f);
        }
    }
}

// fp32-out variant (q and k paths); C = channel stride of BOTH in and out
__global__ __launch_bounds__(320) void dwconv3x3_v3(
    const float* __restrict__ X, const float* __restrict__ Wd,
    float* __restrict__ Y, int C)
{
    __shared__ float4 s[10][W4];
    const int b = blockIdx.z, ch = blockIdx.y;
    const int r0 = blockIdx.x * 8;
    const int tx = threadIdx.x, ty = threadIdx.y;
    const int t  = ty * W4 + tx;
    const float* xp = X + ((size_t)b * C + ch) * HW;
    dw_stage(s, xp, r0, t);
    __syncthreads();
    float4 o = dw_compute_row4(s, tx, ty, Wd + ch * 9);
    ((float4*)(Y + ((size_t)b * C + ch) * HW))[(r0 + ty) * W4 + tx] = o;
}

// fp16-out variant (v path): input stride KVDIM (X pre-offset), out CDIM-dense
__global__ __launch_bounds__(320) void dwconv3x3_v3h(
    const float* __restrict__ X, const float* __restrict__ Wd,
    __half* __restrict__ Yh)
{
    __shared__ float4 s[10][W4];
    const int b = blockIdx.z, ch = blockIdx.y;
    const int r0 = blockIdx.x * 8;
    const int tx = threadIdx.x, ty = threadIdx.y;
    const int t  = ty * W4 + tx;
    const float* xp = X + ((size_t)b * KVDIM + ch) * HW;
    dw_stage(s, xp, r0, t);
    __syncthreads();
    float4 o = dw_compute_row4(s, tx, ty, Wd + ch * 9);
    __half2 p0 = __floats2half2_rn(o.x, o.y);
    __half2 p1 = __floats2half2_rn(o.z, o.w);
    uint2 pk = make_uint2(*(uint32_t*)&p0, *(uint32_t*)&p1);
    *(uint2*)(Yh + ((size_t)b * CDIM + ch) * HW + (r0 + ty) * WIDTH + tx * 4) = pk;
}

// ---------------- zero the gram accumulators -------------------------------
__global__ void zero_acc() {
    int i = blockIdx.x * 256 + threadIdx.x;
    const int nS = BATCH * HEADS * CPH * CPH;
    const int nN = BATCH * HEADS * CPH;
    if (i < nS) g_S[i] = 0.f;
    if (i < nN) { g_NQ[i] = 0.f; g_NK[i] = 0.f; }
}

// ---------------- Gram: S[b,h,c,d] = sum_n q[c,n] k[d,n]; plus sum q^2, k^2
__global__ __launch_bounds__(256) void gram(
    const float* __restrict__ Q, const float* __restrict__ K)
{
    __shared__ float qs[32][33];
    __shared__ float ks[32][33];
    const int b = blockIdx.z, hh = blockIdx.y, split = blockIdx.x;
    const int tid = threadIdx.x;
    const float* qb = Q + ((size_t)b * CDIM  + hh * CPH) * HW;
    const float* kb = K + ((size_t)b * KVDIM + hh * CPH) * HW;
    const int chunk = HW / NSPLIT;
    const int nbeg = split * chunk;
    const int ty = tid >> 4, tx = tid & 15;
    const int lc = tid >> 3;
    const int lj = (tid & 7) * 4;

    float acc00 = 0, acc01 = 0, acc10 = 0, acc11 = 0;
    float aq0 = 0, aq1 = 0, ak0 = 0, ak1 = 0;

    for (int n0 = nbeg; n0 < nbeg + chunk; n0 += 32) {
        float4 vq = *(const float4*)&qb[(size_t)lc * HW + n0 + lj];
        float4 vk = *(const float4*)&kb[(size_t)lc * HW + n0 + lj];
        qs[lc][lj] = vq.x; qs[lc][lj+1] = vq.y; qs[lc][lj+2] = vq.z; qs[lc][lj+3] = vq.w;
        ks[lc][lj] = vk.x; ks[lc][lj+1] = vk.y; ks[lc][lj+2] = vk.z; ks[lc][lj+3] = vk.w;
        __syncthreads();
        #pragma unroll
        for (int t = 0; t < 32; t++) {
            float q0 = qs[ty*2][t],  q1 = qs[ty*2+1][t];
            float k0 = ks[tx*2][t],  k1 = ks[tx*2+1][t];
            acc00 += q0*k0; acc01 += q0*k1; acc10 += q1*k0; acc11 += q1*k1;
            if (tx == 0) { aq0 += q0*q0; aq1 += q1*q1; }
            if (ty == 0) { ak0 += k0*k0; ak1 += k1*k1; }
        }
        __syncthreads();
    }
    float* Sb = g_S + (size_t)(b * HEADS + hh) * CPH * CPH;
    atomicAdd(&Sb[(ty*2    ) * CPH + tx*2    ], acc00);
    atomicAdd(&Sb[(ty*2    ) * CPH + tx*2 + 1], acc01);
    atomicAdd(&Sb[(ty*2 + 1) * CPH + tx*2    ], acc10);
    atomicAdd(&Sb[(ty*2 + 1) * CPH + tx*2 + 1], acc11);
    if (tx == 0) {
        atomicAdd(&g_NQ[(b * HEADS + hh) * CPH + ty*2    ], aq0);
        atomicAdd(&g_NQ[(b * HEADS + hh) * CPH + ty*2 + 1], aq1);
    }
    if (ty == 0) {
        atomicAdd(&g_NK[(b * HEADS + hh) * CPH + tx*2    ], ak0);
        atomicAdd(&g_NK[(b * HEADS + hh) * CPH + tx*2 + 1], ak1);
    }
}

// ---------------- softmax over d with L2-norm scaling + temperature --------
__global__ void softmax_attn(const float* __restrict__ temp) {
    const int bh = blockIdx.x;
    const int h  = bh % HEADS;
    const int d  = threadIdx.x;
    const float t = temp[h];
    float nk = fmaxf(sqrtf(g_NK[bh * CPH + d]), 1e-12f);
    for (int c = 0; c < CPH; c++) {
        float nq = fmaxf(sqrtf(g_NQ[bh * CPH + c]), 1e-12f);
        float v = g_S[bh * CPH * CPH + c * CPH + d] / (nq * nk) * t;
        float m = v;
        #pragma unroll
        for (int o = 16; o; o >>= 1) m = fmaxf(m, __shfl_xor_sync(~0u, m, o));
        float e = __expf(v - m);
        float s = e;
        #pragma unroll
        for (int o = 16; o; o >>= 1) s += __shfl_xor_sync(~0u, s, o);
        g_A[bh * CPH * CPH + c * CPH + d] = e / s;
    }
}

// ---------------- fold: M[b,o,g] = sum_c Wout[o, h*32+c] * A[b,h,c,d] ------
__global__ __launch_bounds__(256) void foldM(const float* __restrict__ Wout) {
    const int b = blockIdx.y;
    const int idx = blockIdx.x * 256 + threadIdx.x;
    const int o = idx / CDIM, g = idx % CDIM;
    const int h = g / CPH, d = g % CPH;
    const float* Ab = g_A + (size_t)(b * HEADS + h) * CPH * CPH;
    float acc = 0.f;
    #pragma unroll
    for (int c = 0; c < CPH; c++)
        acc += Wout[o * CDIM + h * CPH + c] * Ab[c * CPH + d];
    g_M16[(size_t)b * CDIM * CDIM + idx] = __float2half_rn(acc);
}

// ---------------- launch --------------------------------------------------
extern "C" void kernel_launch(void* const* d_in, const int* in_sizes, int n_in,
                              void* d_out, int out_size)
{
    const float* x_q   = (const float*)d_in[0];
    const float* x_kv  = (const float*)d_in[1];
    const float* w_q   = (const float*)d_in[2];
    const float* w_kv  = (const float*)d_in[3];
    const float* w_qdw = (const float*)d_in[4];
    const float* w_kvdw= (const float*)d_in[5];
    const float* w_out = (const float*)d_in[6];
    const float* temp  = (const float*)d_in[7];
    float* out = (float*)d_out;

    float *bq, *bkv, *bqd, *bkvd;
    __half *wq16, *wkv16, *m16, *xq16, *xkv16, *v16;
    cudaGetSymbolAddress((void**)&bq,    g_q);
    cudaGetSymbolAddress((void**)&bkv,   g_kv);
    cudaGetSymbolAddress((void**)&bqd,   g_qd);
    cudaGetSymbolAddress((void**)&bkvd,  g_kvd);
    cudaGetSymbolAddress((void**)&wq16,  g_Wq16);
    cudaGetSymbolAddress((void**)&wkv16, g_Wkv16);
    cudaGetSymbolAddress((void**)&m16,   g_M16);
    cudaGetSymbolAddress((void**)&xq16,  g_Xq16);
    cudaGetSymbolAddress((void**)&xkv16, g_Xkv16);
    cudaGetSymbolAddress((void**)&v16,   g_V16);

    cudaFuncSetAttribute(gemm_fp16, cudaFuncAttributeMaxDynamicSharedMemorySize, SM_TOTAL);

    // 0) convert weights + activations to fp16
    convert_w<<<(KVDIM * CDIM + 255) / 256, 256>>>(w_q, w_kv);
    convert_x<<<(int)(((size_t)BATCH * CDIM * HW / 4) / 256), 256>>>(x_q, x_kv);
    // 1) q = W_q @ x_q
    gemm_fp16<<<dim3(HW/128, CDIM/64, BATCH), 256, SM_TOTAL>>>(
        wq16, xq16, bq, CDIM, 0, (long)CDIM * HW);
    // 2) kv = W_kv @ x_kv (384 outputs)
    gemm_fp16<<<dim3(HW/128, KVDIM/64, BATCH), 256, SM_TOTAL>>>(
        wkv16, xkv16, bkv, KVDIM, 0, (long)CDIM * HW);
    // 3) depthwise 3x3 (vectorized): q (fp32), k (fp32), v (fp16 out)
    {
        dim3 blk(W4, 8);
        dwconv3x3_v3 <<<dim3(WIDTH/8, CDIM, BATCH), blk>>>(bq, w_qdw, bqd, CDIM);
        dwconv3x3_v3 <<<dim3(WIDTH/8, CDIM, BATCH), blk>>>(bkv, w_kvdw, bkvd, KVDIM);
        dwconv3x3_v3h<<<dim3(WIDTH/8, CDIM, BATCH), blk>>>(
            bkv + (size_t)CDIM * HW, w_kvdw + CDIM * 9, v16);
    }
    // 4) zero gram accumulators
    zero_acc<<<(BATCH*HEADS*CPH*CPH + 255)/256, 256>>>();
    // 5) gram + norms (k = first KVDIM-strided half of kvd)
    gram<<<dim3(NSPLIT, HEADS, BATCH), 256>>>(bqd, bkvd);
    // 6) softmax with normalization + temperature
    softmax_attn<<<BATCH * HEADS, 32>>>(temp);
    // 7) fold W_out with attention -> fp16 M
    foldM<<<dim3(CDIM*CDIM/256, BATCH), 256>>>(w_out);
    // 8) out = M_b @ v
    gemm_fp16<<<dim3(HW/128, CDIM/64, BATCH), 256, SM_TOTAL>>>(
        m16, v16, out, CDIM, (long)CDIM * CDIM, (long)CDIM * HW);
}